// round 1
// baseline (speedup 1.0000x reference)
#include <cuda_runtime.h>
#include <math.h>
#include <stdint.h>

// Problem constants (fixed shapes from reference)
#define S_TOK 2048      // B*T
#define H_DIM 1024
#define N_EXP 16
#define FF    1024
#define FF2   2048
#define TOPK  4
#define CLIPV 7.0f
#define AUX_COEF 0.02f

// ---------------- scratch (static device globals; no allocations) -------------
__device__ float g_act[8192 * 1024];          // compact activated rows [sum n_e = S*TOPK = 8192][FF]
__device__ int   g_topk_i[S_TOK * TOPK];
__device__ float g_topk_w[S_TOK * TOPK];
__device__ float g_imp[N_EXP];                // sum of softmax probs per expert
__device__ int   g_loadcnt[N_EXP];            // histogram of argmax-position (only 0..3 used)
__device__ int   g_ecnt[N_EXP];
__device__ int   g_eoff[N_EXP];
__device__ int   g_etok[N_EXP * S_TOK];
__device__ float g_egw[N_EXP * S_TOK];

// ---------------- f32x2 packed math (Blackwell sm_100a) -----------------------
__device__ __forceinline__ unsigned long long pk2(float lo, float hi) {
  unsigned long long r;
  asm("mov.b64 %0, {%1, %2};" : "=l"(r) : "f"(lo), "f"(hi));
  return r;
}
__device__ __forceinline__ float2 upk2(unsigned long long v) {
  float lo, hi;
  asm("mov.b64 {%0, %1}, %2;" : "=f"(lo), "=f"(hi) : "l"(v));
  return make_float2(lo, hi);
}
#define FFMA2(acc, a, b) asm("fma.rn.f32x2 %0, %1, %2, %0;" : "+l"(acc) : "l"(a), "l"(b))

// ---------------- K0: zero output + small accumulators ------------------------
__global__ void init_kernel(float* __restrict__ out, int out_size) {
  int i = blockIdx.x * blockDim.x + threadIdx.x;
  if (i < out_size) out[i] = 0.f;
  if (i < N_EXP) { g_imp[i] = 0.f; g_loadcnt[i] = 0; }
}

// ---------------- K1: router -------------------------------------------------
// One block per token. Computes logits (fp32 exact), top-4 (JAX tie-break:
// strict '>' keeps lowest index), top-4 softmax weights, full softmax for
// importance (atomic accumulate), and the faithful load term:
// one_hot(argmax over k of topk_i) histogram.
__global__ __launch_bounds__(256) void router_kernel(
    const float* __restrict__ x, const float* __restrict__ rw,
    const float* __restrict__ rb) {
  int s = blockIdx.x;
  __shared__ __align__(16) float xs[H_DIM];
  __shared__ float lg[N_EXP];

  const float* xr = x + (size_t)s * H_DIM;
  {
    int i = threadIdx.x;                  // 256 threads * 1 float4 = 1024 floats
    ((float4*)xs)[i] = ((const float4*)xr)[i];
  }
  __syncthreads();

  int w = threadIdx.x >> 5, lane = threadIdx.x & 31;
  for (int e = w; e < N_EXP; e += 8) {
    const float4* wr = (const float4*)(rw + (size_t)e * H_DIM);
    float sum = 0.f;
    for (int i = lane; i < H_DIM / 4; i += 32) {
      float4 xv = ((const float4*)xs)[i];
      float4 wv = wr[i];
      sum += xv.x * wv.x + xv.y * wv.y + xv.z * wv.z + xv.w * wv.w;
    }
#pragma unroll
    for (int o = 16; o; o >>= 1) sum += __shfl_xor_sync(0xffffffffu, sum, o);
    if (lane == 0) lg[e] = sum + rb[e];
  }
  __syncthreads();

  if (threadIdx.x == 0) {
    float l[N_EXP];
#pragma unroll
    for (int e = 0; e < N_EXP; e++) l[e] = lg[e];

    // top-4 selection (descending; ties -> lower index first)
    int idx[TOPK]; float val[TOPK];
    bool used[N_EXP];
#pragma unroll
    for (int e = 0; e < N_EXP; e++) used[e] = false;
#pragma unroll
    for (int k = 0; k < TOPK; k++) {
      float best = -3.4e38f; int bi = 0;
      for (int e = 0; e < N_EXP; e++)
        if (!used[e] && l[e] > best) { best = l[e]; bi = e; }
      idx[k] = bi; val[k] = best; used[bi] = true;
    }
    // softmax over top-4 (val[0] is max)
    float ex[TOPK], se = 0.f;
#pragma unroll
    for (int k = 0; k < TOPK; k++) { ex[k] = expf(val[k] - val[0]); se += ex[k]; }
#pragma unroll
    for (int k = 0; k < TOPK; k++) {
      g_topk_i[s * TOPK + k] = idx[k];
      g_topk_w[s * TOPK + k] = ex[k] / se;
    }
    // full softmax -> importance accumulation
    float mx = l[0];
#pragma unroll
    for (int e = 1; e < N_EXP; e++) mx = fmaxf(mx, l[e]);
    float p[N_EXP], ss = 0.f;
#pragma unroll
    for (int e = 0; e < N_EXP; e++) { p[e] = expf(l[e] - mx); ss += p[e]; }
    float inv = 1.f / ss;
#pragma unroll
    for (int e = 0; e < N_EXP; e++) atomicAdd(&g_imp[e], p[e] * inv);
    // load: argmax over k of topk indices -> position j in [0,4)
    int j = 0, bv = idx[0];
#pragma unroll
    for (int k = 1; k < TOPK; k++)
      if (idx[k] > bv) { bv = idx[k]; j = k; }
    atomicAdd(&g_loadcnt[j], 1);
  }
}

// ---------------- K2: deterministic per-expert token lists + offsets ----------
__global__ void build_lists_kernel() {
  int e = threadIdx.x >> 5;   // 16 warps, one per expert
  int lane = threadIdx.x & 31;
  int base = 0;
  for (int t0 = 0; t0 < S_TOK; t0 += 32) {
    int s = t0 + lane;
    bool has = false; float w = 0.f;
#pragma unroll
    for (int k = 0; k < TOPK; k++) {
      if (g_topk_i[s * TOPK + k] == e) { has = true; w = g_topk_w[s * TOPK + k]; }
    }
    unsigned mask = __ballot_sync(0xffffffffu, has);
    if (has) {
      int pos = base + __popc(mask & ((1u << lane) - 1u));
      g_etok[e * S_TOK + pos] = s;
      g_egw[e * S_TOK + pos] = w;
    }
    base += __popc(mask);
  }
  if (lane == 0) g_ecnt[e] = base;
  __syncthreads();
  if (threadIdx.x == 0) {
    int off = 0;
    for (int i = 0; i < N_EXP; i++) { g_eoff[i] = off; off += g_ecnt[i]; }
  }
}

// ---------------- K3: aux loss scalar ------------------------------------------
__global__ void aux_kernel(float* __restrict__ out, int out_size) {
  if (threadIdx.x == 0 && blockIdx.x == 0) {
    const float invS = 1.f / (float)S_TOK;
    float a = 0.f;
    for (int e = 0; e < N_EXP; e++)
      a += (g_imp[e] * invS) * ((float)g_loadcnt[e] * invS);
    out[out_size - 1] = AUX_COEF * (float)N_EXP * a;
  }
}

// ---------------- GEMM1: h = gather(x) @ W_in[e], fused SwiGLU -> g_act -------
// Tile: 128 rows x 64 ff-cols (both up and gate columns), TK=16, 256 threads,
// thread tile 8x4 outputs x {up,gate}. Double-buffered SMEM, f32x2 FMAs.
__global__ __launch_bounds__(256) void gemm1_kernel(
    const float* __restrict__ x, const float* __restrict__ W_in,
    const float* __restrict__ b_in) {
  const int e = blockIdx.z;
  const int ne = g_ecnt[e];
  const int row0 = blockIdx.y * 128;
  if (row0 >= ne) return;
  const int n0 = blockIdx.x * 64;
  const int tid = threadIdx.x;

  __shared__ __align__(16) float As[2][16][132];
  __shared__ __align__(16) float Bu[2][16][64];
  __shared__ __align__(16) float Bg[2][16][64];

  // A load mapping: this thread loads rows (am, am+64), k-chunk ak..ak+3
  const int am = tid >> 2;
  const int ak = (tid & 3) * 4;
  int pos0 = row0 + am, pos1 = row0 + am + 64;
  int tok0 = (pos0 < ne) ? g_etok[e * S_TOK + pos0] : 0;
  int tok1 = (pos1 < ne) ? g_etok[e * S_TOK + pos1] : 0;
  const float* ap0 = x + (size_t)tok0 * H_DIM + ak;
  const float* ap1 = x + (size_t)tok1 * H_DIM + ak;

  // B load mapping: row bk (0..15), cols bn..bn+3
  const int bk = tid >> 4;
  const int bn = (tid & 15) * 4;
  const float* bup = W_in + (size_t)e * H_DIM * FF2 + (size_t)bk * FF2 + n0 + bn;
  const float* bgp = bup + FF;

  float4 ra0 = *(const float4*)ap0;
  float4 ra1 = *(const float4*)ap1;
  float4 rbu = *(const float4*)bup;
  float4 rbg = *(const float4*)bgp;

  unsigned long long au[8][2], ag[8][2];
#pragma unroll
  for (int i = 0; i < 8; i++) { au[i][0] = au[i][1] = ag[i][0] = ag[i][1] = 0ull; }

  const int ty = tid >> 4, tx = tid & 15;
  int buf = 0;
  for (int kb = 0; kb < H_DIM / 16; kb++) {
    As[buf][ak + 0][am] = ra0.x;
    As[buf][ak + 1][am] = ra0.y;
    As[buf][ak + 2][am] = ra0.z;
    As[buf][ak + 3][am] = ra0.w;
    As[buf][ak + 0][am + 64] = ra1.x;
    As[buf][ak + 1][am + 64] = ra1.y;
    As[buf][ak + 2][am + 64] = ra1.z;
    As[buf][ak + 3][am + 64] = ra1.w;
    *(float4*)&Bu[buf][bk][bn] = rbu;
    *(float4*)&Bg[buf][bk][bn] = rbg;
    __syncthreads();
    if (kb < H_DIM / 16 - 1) {
      ra0 = *(const float4*)(ap0 + (kb + 1) * 16);
      ra1 = *(const float4*)(ap1 + (kb + 1) * 16);
      rbu = *(const float4*)(bup + (size_t)(kb + 1) * 16 * FF2);
      rbg = *(const float4*)(bgp + (size_t)(kb + 1) * 16 * FF2);
    }
#pragma unroll
    for (int k = 0; k < 16; k++) {
      float4 a0 = *(const float4*)&As[buf][k][ty * 4];
      float4 a1 = *(const float4*)&As[buf][k][ty * 4 + 64];
      const unsigned long long* bup64 = (const unsigned long long*)&Bu[buf][k][tx * 4];
      const unsigned long long* bgp64 = (const unsigned long long*)&Bg[buf][k][tx * 4];
      unsigned long long bu01 = bup64[0], bu23 = bup64[1];
      unsigned long long bg01 = bgp64[0], bg23 = bgp64[1];
      unsigned long long ad[8];
      ad[0] = pk2(a0.x, a0.x); ad[1] = pk2(a0.y, a0.y);
      ad[2] = pk2(a0.z, a0.z); ad[3] = pk2(a0.w, a0.w);
      ad[4] = pk2(a1.x, a1.x); ad[5] = pk2(a1.y, a1.y);
      ad[6] = pk2(a1.z, a1.z); ad[7] = pk2(a1.w, a1.w);
#pragma unroll
      for (int r = 0; r < 8; r++) {
        FFMA2(au[r][0], ad[r], bu01);
        FFMA2(au[r][1], ad[r], bu23);
        FFMA2(ag[r][0], ad[r], bg01);
        FFMA2(ag[r][1], ad[r], bg23);
      }
    }
    buf ^= 1;
  }

  // epilogue: bias, clip, silu(gate)*up -> compact act scratch
  const float* bi_u = b_in + (size_t)e * FF2 + n0 + tx * 4;
  const float* bi_g = bi_u + FF;
  const int goff = g_eoff[e];
#pragma unroll
  for (int sel = 0; sel < 2; sel++) {
#pragma unroll
    for (int j = 0; j < 4; j++) {
      int m = ty * 4 + sel * 64 + j;
      int pos = row0 + m;
      if (pos >= ne) continue;
      int r = sel * 4 + j;
      float2 u0 = upk2(au[r][0]), u1 = upk2(au[r][1]);
      float2 q0 = upk2(ag[r][0]), q1 = upk2(ag[r][1]);
      float up[4] = {u0.x, u0.y, u1.x, u1.y};
      float gt[4] = {q0.x, q0.y, q1.x, q1.y};
      float res[4];
#pragma unroll
      for (int q = 0; q < 4; q++) {
        float uu = up[q] + bi_u[q];
        float gv = gt[q] + bi_g[q];
        uu = fminf(fmaxf(uu, -CLIPV), CLIPV);
        gv = fminf(fmaxf(gv, -CLIPV), CLIPV);
        float sig = 1.f / (1.f + expf(-gv));
        res[q] = gv * sig * uu;
      }
      float* arow = g_act + (size_t)(goff + pos) * FF + n0 + tx * 4;
      *(float4*)arow = make_float4(res[0], res[1], res[2], res[3]);
    }
  }
}

// ---------------- GEMM2: eo = act @ W_out[e] + b_out; out += gw * eo ----------
// Tile: 128 x 128, TK=16, 256 threads, thread tile 8x8, fused combine via atomics.
__global__ __launch_bounds__(256) void gemm2_kernel(
    const float* __restrict__ W_out, const float* __restrict__ b_out,
    float* __restrict__ out) {
  const int e = blockIdx.z;
  const int ne = g_ecnt[e];
  const int row0 = blockIdx.y * 128;
  if (row0 >= ne) return;
  const int n0 = blockIdx.x * 128;
  const int tid = threadIdx.x;
  const int goff = g_eoff[e];

  __shared__ __align__(16) float As[2][16][132];
  __shared__ __align__(16) float Bs[2][16][128];

  const int am = tid >> 2;
  const int ak = (tid & 3) * 4;
  int pos0 = row0 + am, pos1 = row0 + am + 64;
  const float* ap0 = g_act + (size_t)(goff + (pos0 < ne ? pos0 : 0)) * FF + ak;
  const float* ap1 = g_act + (size_t)(goff + (pos1 < ne ? pos1 : 0)) * FF + ak;

  const int bk = tid >> 5;            // 0..7 (loads rows bk and bk+8)
  const int bn = (tid & 31) * 4;      // 0..124
  const float* bp = W_out + (size_t)e * FF * H_DIM + (size_t)bk * H_DIM + n0 + bn;

  float4 ra0 = *(const float4*)ap0;
  float4 ra1 = *(const float4*)ap1;
  float4 rb0 = *(const float4*)bp;
  float4 rb1 = *(const float4*)(bp + 8 * H_DIM);

  unsigned long long acc[8][4];
#pragma unroll
  for (int i = 0; i < 8; i++)
#pragma unroll
    for (int c = 0; c < 4; c++) acc[i][c] = 0ull;

  const int ty = tid >> 4, tx = tid & 15;
  int buf = 0;
  for (int kb = 0; kb < FF / 16; kb++) {
    As[buf][ak + 0][am] = ra0.x;
    As[buf][ak + 1][am] = ra0.y;
    As[buf][ak + 2][am] = ra0.z;
    As[buf][ak + 3][am] = ra0.w;
    As[buf][ak + 0][am + 64] = ra1.x;
    As[buf][ak + 1][am + 64] = ra1.y;
    As[buf][ak + 2][am + 64] = ra1.z;
    As[buf][ak + 3][am + 64] = ra1.w;
    *(float4*)&Bs[buf][bk][bn] = rb0;
    *(float4*)&Bs[buf][bk + 8][bn] = rb1;
    __syncthreads();
    if (kb < FF / 16 - 1) {
      ra0 = *(const float4*)(ap0 + (kb + 1) * 16);
      ra1 = *(const float4*)(ap1 + (kb + 1) * 16);
      rb0 = *(const float4*)(bp + (size_t)(kb + 1) * 16 * H_DIM);
      rb1 = *(const float4*)(bp + (size_t)((kb + 1) * 16 + 8) * H_DIM);
    }
#pragma unroll
    for (int k = 0; k < 16; k++) {
      float4 a0 = *(const float4*)&As[buf][k][ty * 4];
      float4 a1 = *(const float4*)&As[buf][k][ty * 4 + 64];
      const unsigned long long* b64a = (const unsigned long long*)&Bs[buf][k][tx * 4];
      const unsigned long long* b64b = (const unsigned long long*)&Bs[buf][k][tx * 4 + 64];
      unsigned long long b00 = b64a[0], b01 = b64a[1];
      unsigned long long b10 = b64b[0], b11 = b64b[1];
      unsigned long long ad[8];
      ad[0] = pk2(a0.x, a0.x); ad[1] = pk2(a0.y, a0.y);
      ad[2] = pk2(a0.z, a0.z); ad[3] = pk2(a0.w, a0.w);
      ad[4] = pk2(a1.x, a1.x); ad[5] = pk2(a1.y, a1.y);
      ad[6] = pk2(a1.z, a1.z); ad[7] = pk2(a1.w, a1.w);
#pragma unroll
      for (int r = 0; r < 8; r++) {
        FFMA2(acc[r][0], ad[r], b00);
        FFMA2(acc[r][1], ad[r], b01);
        FFMA2(acc[r][2], ad[r], b10);
        FFMA2(acc[r][3], ad[r], b11);
      }
    }
    buf ^= 1;
  }

  // epilogue: add b_out, scale by gate weight, atomic combine into out
#pragma unroll
  for (int sel = 0; sel < 2; sel++) {
#pragma unroll
    for (int j = 0; j < 4; j++) {
      int m = ty * 4 + sel * 64 + j;
      int pos = row0 + m;
      if (pos >= ne) continue;
      int r = sel * 4 + j;
      int tok = g_etok[e * S_TOK + pos];
      float gw = g_egw[e * S_TOK + pos];
      float* orow = out + (size_t)tok * H_DIM;
      const float* bo = b_out + (size_t)e * H_DIM;
#pragma unroll
      for (int c = 0; c < 4; c++) {
        float2 v = upk2(acc[r][c]);
        int n = n0 + tx * 4 + (c >> 1) * 64 + (c & 1) * 2;
        atomicAdd(orow + n,     gw * (v.x + bo[n]));
        atomicAdd(orow + n + 1, gw * (v.y + bo[n + 1]));
      }
    }
  }
}

// ---------------- launcher -----------------------------------------------------
extern "C" void kernel_launch(void* const* d_in, const int* in_sizes, int n_in,
                              void* d_out, int out_size) {
  const float* x     = (const float*)d_in[0];
  const float* W_in  = (const float*)d_in[1];
  const float* b_in  = (const float*)d_in[2];
  const float* W_out = (const float*)d_in[3];
  const float* b_out = (const float*)d_in[4];
  const float* rw    = (const float*)d_in[5];
  const float* rb    = (const float*)d_in[6];
  float* out = (float*)d_out;

  init_kernel<<<(out_size + 255) / 256, 256>>>(out, out_size);
  router_kernel<<<S_TOK, 256>>>(x, rw, rb);
  build_lists_kernel<<<1, 512>>>();
  aux_kernel<<<1, 32>>>(out, out_size);
  // GEMM1: grid x = FF/64 tiles, y = worst-case row tiles (2048/128), z = experts
  gemm1_kernel<<<dim3(FF / 64, S_TOK / 128, N_EXP), 256>>>(x, W_in, b_in);
  // GEMM2: grid x = H/128 tiles
  gemm2_kernel<<<dim3(H_DIM / 128, S_TOK / 128, N_EXP), 256>>>(W_out, b_out, out);
}

// round 2
// speedup vs baseline: 1.0000x; 1.0000x over previous
#include <cuda_runtime.h>
#include <math.h>
#include <stdint.h>

// Problem constants (fixed shapes from reference)
#define S_TOK 2048      // B*T
#define H_DIM 1024
#define N_EXP 16
#define FF    1024
#define FF2   2048
#define TOPK  4
#define CLIPV 7.0f
#define AUX_COEF 0.02f

// ---------------- scratch (static device globals; no allocations) -------------
__device__ float g_act[8192 * 1024];          // compact activated rows [sum n_e = S*TOPK = 8192][FF]
__device__ int   g_topk_i[S_TOK * TOPK];
__device__ float g_topk_w[S_TOK * TOPK];
__device__ float g_imp[N_EXP];                // sum of softmax probs per expert
__device__ int   g_loadcnt[N_EXP];            // histogram of argmax-position (only 0..3 used)
__device__ int   g_ecnt[N_EXP];
__device__ int   g_eoff[N_EXP];
__device__ int   g_etok[N_EXP * S_TOK];
__device__ float g_egw[N_EXP * S_TOK];

// ---------------- f32x2 packed math (Blackwell sm_100a) -----------------------
__device__ __forceinline__ unsigned long long pk2(float lo, float hi) {
  unsigned long long r;
  asm("mov.b64 %0, {%1, %2};" : "=l"(r) : "f"(lo), "f"(hi));
  return r;
}
__device__ __forceinline__ float2 upk2(unsigned long long v) {
  float lo, hi;
  asm("mov.b64 {%0, %1}, %2;" : "=f"(lo), "=f"(hi) : "l"(v));
  return make_float2(lo, hi);
}
#define FFMA2(acc, a, b) asm("fma.rn.f32x2 %0, %1, %2, %0;" : "+l"(acc) : "l"(a), "l"(b))

// ---------------- K0: zero output + small accumulators ------------------------
__global__ void init_kernel(float* __restrict__ out, int out_size) {
  int i = blockIdx.x * blockDim.x + threadIdx.x;
  if (i < out_size) out[i] = 0.f;
  if (i < N_EXP) { g_imp[i] = 0.f; g_loadcnt[i] = 0; }
}

// ---------------- K1: router -------------------------------------------------
// One block per token. Computes logits (fp32 exact), top-4 (JAX tie-break:
// strict '>' keeps lowest index), top-4 softmax weights, full softmax for
// importance (atomic accumulate), and the faithful load term:
// one_hot(argmax over k of topk_i) histogram.
__global__ __launch_bounds__(256) void router_kernel(
    const float* __restrict__ x, const float* __restrict__ rw,
    const float* __restrict__ rb) {
  int s = blockIdx.x;
  __shared__ __align__(16) float xs[H_DIM];
  __shared__ float lg[N_EXP];

  const float* xr = x + (size_t)s * H_DIM;
  {
    int i = threadIdx.x;                  // 256 threads * 1 float4 = 1024 floats
    ((float4*)xs)[i] = ((const float4*)xr)[i];
  }
  __syncthreads();

  int w = threadIdx.x >> 5, lane = threadIdx.x & 31;
  for (int e = w; e < N_EXP; e += 8) {
    const float4* wr = (const float4*)(rw + (size_t)e * H_DIM);
    float sum = 0.f;
    for (int i = lane; i < H_DIM / 4; i += 32) {
      float4 xv = ((const float4*)xs)[i];
      float4 wv = wr[i];
      sum += xv.x * wv.x + xv.y * wv.y + xv.z * wv.z + xv.w * wv.w;
    }
#pragma unroll
    for (int o = 16; o; o >>= 1) sum += __shfl_xor_sync(0xffffffffu, sum, o);
    if (lane == 0) lg[e] = sum + rb[e];
  }
  __syncthreads();

  if (threadIdx.x == 0) {
    float l[N_EXP];
#pragma unroll
    for (int e = 0; e < N_EXP; e++) l[e] = lg[e];

    // top-4 selection (descending; ties -> lower index first)
    int idx[TOPK]; float val[TOPK];
    bool used[N_EXP];
#pragma unroll
    for (int e = 0; e < N_EXP; e++) used[e] = false;
#pragma unroll
    for (int k = 0; k < TOPK; k++) {
      float best = -3.4e38f; int bi = 0;
      for (int e = 0; e < N_EXP; e++)
        if (!used[e] && l[e] > best) { best = l[e]; bi = e; }
      idx[k] = bi; val[k] = best; used[bi] = true;
    }
    // softmax over top-4 (val[0] is max)
    float ex[TOPK], se = 0.f;
#pragma unroll
    for (int k = 0; k < TOPK; k++) { ex[k] = expf(val[k] - val[0]); se += ex[k]; }
#pragma unroll
    for (int k = 0; k < TOPK; k++) {
      g_topk_i[s * TOPK + k] = idx[k];
      g_topk_w[s * TOPK + k] = ex[k] / se;
    }
    // full softmax -> importance accumulation
    float mx = l[0];
#pragma unroll
    for (int e = 1; e < N_EXP; e++) mx = fmaxf(mx, l[e]);
    float p[N_EXP], ss = 0.f;
#pragma unroll
    for (int e = 0; e < N_EXP; e++) { p[e] = expf(l[e] - mx); ss += p[e]; }
    float inv = 1.f / ss;
#pragma unroll
    for (int e = 0; e < N_EXP; e++) atomicAdd(&g_imp[e], p[e] * inv);
    // load: argmax over k of topk indices -> position j in [0,4)
    int j = 0, bv = idx[0];
#pragma unroll
    for (int k = 1; k < TOPK; k++)
      if (idx[k] > bv) { bv = idx[k]; j = k; }
    atomicAdd(&g_loadcnt[j], 1);
  }
}

// ---------------- K2: deterministic per-expert token lists + offsets ----------
__global__ void build_lists_kernel() {
  int e = threadIdx.x >> 5;   // 16 warps, one per expert
  int lane = threadIdx.x & 31;
  int base = 0;
  for (int t0 = 0; t0 < S_TOK; t0 += 32) {
    int s = t0 + lane;
    bool has = false; float w = 0.f;
#pragma unroll
    for (int k = 0; k < TOPK; k++) {
      if (g_topk_i[s * TOPK + k] == e) { has = true; w = g_topk_w[s * TOPK + k]; }
    }
    unsigned mask = __ballot_sync(0xffffffffu, has);
    if (has) {
      int pos = base + __popc(mask & ((1u << lane) - 1u));
      g_etok[e * S_TOK + pos] = s;
      g_egw[e * S_TOK + pos] = w;
    }
    base += __popc(mask);
  }
  if (lane == 0) g_ecnt[e] = base;
  __syncthreads();
  if (threadIdx.x == 0) {
    int off = 0;
    for (int i = 0; i < N_EXP; i++) { g_eoff[i] = off; off += g_ecnt[i]; }
  }
}

// ---------------- K3: aux loss scalar ------------------------------------------
__global__ void aux_kernel(float* __restrict__ out, int out_size) {
  if (threadIdx.x == 0 && blockIdx.x == 0) {
    const float invS = 1.f / (float)S_TOK;
    float a = 0.f;
    for (int e = 0; e < N_EXP; e++)
      a += (g_imp[e] * invS) * ((float)g_loadcnt[e] * invS);
    out[out_size - 1] = AUX_COEF * (float)N_EXP * a;
  }
}

// ---------------- GEMM1: h = gather(x) @ W_in[e], fused SwiGLU -> g_act -------
// Tile: 128 rows x 64 ff-cols (both up and gate columns), TK=16, 256 threads,
// thread tile 8x4 outputs x {up,gate}. Double-buffered SMEM, f32x2 FMAs.
__global__ __launch_bounds__(256) void gemm1_kernel(
    const float* __restrict__ x, const float* __restrict__ W_in,
    const float* __restrict__ b_in) {
  const int e = blockIdx.z;
  const int ne = g_ecnt[e];
  const int row0 = blockIdx.y * 128;
  if (row0 >= ne) return;
  const int n0 = blockIdx.x * 64;
  const int tid = threadIdx.x;

  __shared__ __align__(16) float As[2][16][132];
  __shared__ __align__(16) float Bu[2][16][64];
  __shared__ __align__(16) float Bg[2][16][64];

  // A load mapping: this thread loads rows (am, am+64), k-chunk ak..ak+3
  const int am = tid >> 2;
  const int ak = (tid & 3) * 4;
  int pos0 = row0 + am, pos1 = row0 + am + 64;
  int tok0 = (pos0 < ne) ? g_etok[e * S_TOK + pos0] : 0;
  int tok1 = (pos1 < ne) ? g_etok[e * S_TOK + pos1] : 0;
  const float* ap0 = x + (size_t)tok0 * H_DIM + ak;
  const float* ap1 = x + (size_t)tok1 * H_DIM + ak;

  // B load mapping: row bk (0..15), cols bn..bn+3
  const int bk = tid >> 4;
  const int bn = (tid & 15) * 4;
  const float* bup = W_in + (size_t)e * H_DIM * FF2 + (size_t)bk * FF2 + n0 + bn;
  const float* bgp = bup + FF;

  float4 ra0 = *(const float4*)ap0;
  float4 ra1 = *(const float4*)ap1;
  float4 rbu = *(const float4*)bup;
  float4 rbg = *(const float4*)bgp;

  unsigned long long au[8][2], ag[8][2];
#pragma unroll
  for (int i = 0; i < 8; i++) { au[i][0] = au[i][1] = ag[i][0] = ag[i][1] = 0ull; }

  const int ty = tid >> 4, tx = tid & 15;
  int buf = 0;
  for (int kb = 0; kb < H_DIM / 16; kb++) {
    As[buf][ak + 0][am] = ra0.x;
    As[buf][ak + 1][am] = ra0.y;
    As[buf][ak + 2][am] = ra0.z;
    As[buf][ak + 3][am] = ra0.w;
    As[buf][ak + 0][am + 64] = ra1.x;
    As[buf][ak + 1][am + 64] = ra1.y;
    As[buf][ak + 2][am + 64] = ra1.z;
    As[buf][ak + 3][am + 64] = ra1.w;
    *(float4*)&Bu[buf][bk][bn] = rbu;
    *(float4*)&Bg[buf][bk][bn] = rbg;
    __syncthreads();
    if (kb < H_DIM / 16 - 1) {
      ra0 = *(const float4*)(ap0 + (kb + 1) * 16);
      ra1 = *(const float4*)(ap1 + (kb + 1) * 16);
      rbu = *(const float4*)(bup + (size_t)(kb + 1) * 16 * FF2);
      rbg = *(const float4*)(bgp + (size_t)(kb + 1) * 16 * FF2);
    }
#pragma unroll
    for (int k = 0; k < 16; k++) {
      float4 a0 = *(const float4*)&As[buf][k][ty * 4];
      float4 a1 = *(const float4*)&As[buf][k][ty * 4 + 64];
      const unsigned long long* bup64 = (const unsigned long long*)&Bu[buf][k][tx * 4];
      const unsigned long long* bgp64 = (const unsigned long long*)&Bg[buf][k][tx * 4];
      unsigned long long bu01 = bup64[0], bu23 = bup64[1];
      unsigned long long bg01 = bgp64[0], bg23 = bgp64[1];
      unsigned long long ad[8];
      ad[0] = pk2(a0.x, a0.x); ad[1] = pk2(a0.y, a0.y);
      ad[2] = pk2(a0.z, a0.z); ad[3] = pk2(a0.w, a0.w);
      ad[4] = pk2(a1.x, a1.x); ad[5] = pk2(a1.y, a1.y);
      ad[6] = pk2(a1.z, a1.z); ad[7] = pk2(a1.w, a1.w);
#pragma unroll
      for (int r = 0; r < 8; r++) {
        FFMA2(au[r][0], ad[r], bu01);
        FFMA2(au[r][1], ad[r], bu23);
        FFMA2(ag[r][0], ad[r], bg01);
        FFMA2(ag[r][1], ad[r], bg23);
      }
    }
    buf ^= 1;
  }

  // epilogue: bias, clip, silu(gate)*up -> compact act scratch
  const float* bi_u = b_in + (size_t)e * FF2 + n0 + tx * 4;
  const float* bi_g = bi_u + FF;
  const int goff = g_eoff[e];
#pragma unroll
  for (int sel = 0; sel < 2; sel++) {
#pragma unroll
    for (int j = 0; j < 4; j++) {
      int m = ty * 4 + sel * 64 + j;
      int pos = row0 + m;
      if (pos >= ne) continue;
      int r = sel * 4 + j;
      float2 u0 = upk2(au[r][0]), u1 = upk2(au[r][1]);
      float2 q0 = upk2(ag[r][0]), q1 = upk2(ag[r][1]);
      float up[4] = {u0.x, u0.y, u1.x, u1.y};
      float gt[4] = {q0.x, q0.y, q1.x, q1.y};
      float res[4];
#pragma unroll
      for (int q = 0; q < 4; q++) {
        float uu = up[q] + bi_u[q];
        float gv = gt[q] + bi_g[q];
        uu = fminf(fmaxf(uu, -CLIPV), CLIPV);
        gv = fminf(fmaxf(gv, -CLIPV), CLIPV);
        float sig = 1.f / (1.f + expf(-gv));
        res[q] = gv * sig * uu;
      }
      float* arow = g_act + (size_t)(goff + pos) * FF + n0 + tx * 4;
      *(float4*)arow = make_float4(res[0], res[1], res[2], res[3]);
    }
  }
}

// ---------------- GEMM2: eo = act @ W_out[e] + b_out; out += gw * eo ----------
// Tile: 128 x 128, TK=16, 256 threads, thread tile 8x8, fused combine via atomics.
__global__ __launch_bounds__(256) void gemm2_kernel(
    const float* __restrict__ W_out, const float* __restrict__ b_out,
    float* __restrict__ out) {
  const int e = blockIdx.z;
  const int ne = g_ecnt[e];
  const int row0 = blockIdx.y * 128;
  if (row0 >= ne) return;
  const int n0 = blockIdx.x * 128;
  const int tid = threadIdx.x;
  const int goff = g_eoff[e];

  __shared__ __align__(16) float As[2][16][132];
  __shared__ __align__(16) float Bs[2][16][128];

  const int am = tid >> 2;
  const int ak = (tid & 3) * 4;
  int pos0 = row0 + am, pos1 = row0 + am + 64;
  const float* ap0 = g_act + (size_t)(goff + (pos0 < ne ? pos0 : 0)) * FF + ak;
  const float* ap1 = g_act + (size_t)(goff + (pos1 < ne ? pos1 : 0)) * FF + ak;

  const int bk = tid >> 5;            // 0..7 (loads rows bk and bk+8)
  const int bn = (tid & 31) * 4;      // 0..124
  const float* bp = W_out + (size_t)e * FF * H_DIM + (size_t)bk * H_DIM + n0 + bn;

  float4 ra0 = *(const float4*)ap0;
  float4 ra1 = *(const float4*)ap1;
  float4 rb0 = *(const float4*)bp;
  float4 rb1 = *(const float4*)(bp + 8 * H_DIM);

  unsigned long long acc[8][4];
#pragma unroll
  for (int i = 0; i < 8; i++)
#pragma unroll
    for (int c = 0; c < 4; c++) acc[i][c] = 0ull;

  const int ty = tid >> 4, tx = tid & 15;
  int buf = 0;
  for (int kb = 0; kb < FF / 16; kb++) {
    As[buf][ak + 0][am] = ra0.x;
    As[buf][ak + 1][am] = ra0.y;
    As[buf][ak + 2][am] = ra0.z;
    As[buf][ak + 3][am] = ra0.w;
    As[buf][ak + 0][am + 64] = ra1.x;
    As[buf][ak + 1][am + 64] = ra1.y;
    As[buf][ak + 2][am + 64] = ra1.z;
    As[buf][ak + 3][am + 64] = ra1.w;
    *(float4*)&Bs[buf][bk][bn] = rb0;
    *(float4*)&Bs[buf][bk + 8][bn] = rb1;
    __syncthreads();
    if (kb < FF / 16 - 1) {
      ra0 = *(const float4*)(ap0 + (kb + 1) * 16);
      ra1 = *(const float4*)(ap1 + (kb + 1) * 16);
      rb0 = *(const float4*)(bp + (size_t)(kb + 1) * 16 * H_DIM);
      rb1 = *(const float4*)(bp + (size_t)((kb + 1) * 16 + 8) * H_DIM);
    }
#pragma unroll
    for (int k = 0; k < 16; k++) {
      float4 a0 = *(const float4*)&As[buf][k][ty * 4];
      float4 a1 = *(const float4*)&As[buf][k][ty * 4 + 64];
      const unsigned long long* b64a = (const unsigned long long*)&Bs[buf][k][tx * 4];
      const unsigned long long* b64b = (const unsigned long long*)&Bs[buf][k][tx * 4 + 64];
      unsigned long long b00 = b64a[0], b01 = b64a[1];
      unsigned long long b10 = b64b[0], b11 = b64b[1];
      unsigned long long ad[8];
      ad[0] = pk2(a0.x, a0.x); ad[1] = pk2(a0.y, a0.y);
      ad[2] = pk2(a0.z, a0.z); ad[3] = pk2(a0.w, a0.w);
      ad[4] = pk2(a1.x, a1.x); ad[5] = pk2(a1.y, a1.y);
      ad[6] = pk2(a1.z, a1.z); ad[7] = pk2(a1.w, a1.w);
#pragma unroll
      for (int r = 0; r < 8; r++) {
        FFMA2(acc[r][0], ad[r], b00);
        FFMA2(acc[r][1], ad[r], b01);
        FFMA2(acc[r][2], ad[r], b10);
        FFMA2(acc[r][3], ad[r], b11);
      }
    }
    buf ^= 1;
  }

  // epilogue: add b_out, scale by gate weight, atomic combine into out
#pragma unroll
  for (int sel = 0; sel < 2; sel++) {
#pragma unroll
    for (int j = 0; j < 4; j++) {
      int m = ty * 4 + sel * 64 + j;
      int pos = row0 + m;
      if (pos >= ne) continue;
      int r = sel * 4 + j;
      int tok = g_etok[e * S_TOK + pos];
      float gw = g_egw[e * S_TOK + pos];
      float* orow = out + (size_t)tok * H_DIM;
      const float* bo = b_out + (size_t)e * H_DIM;
#pragma unroll
      for (int c = 0; c < 4; c++) {
        float2 v = upk2(acc[r][c]);
        int n = n0 + tx * 4 + (c >> 1) * 64 + (c & 1) * 2;
        atomicAdd(orow + n,     gw * (v.x + bo[n]));
        atomicAdd(orow + n + 1, gw * (v.y + bo[n + 1]));
      }
    }
  }
}

// ---------------- launcher -----------------------------------------------------
extern "C" void kernel_launch(void* const* d_in, const int* in_sizes, int n_in,
                              void* d_out, int out_size) {
  const float* x     = (const float*)d_in[0];
  const float* W_in  = (const float*)d_in[1];
  const float* b_in  = (const float*)d_in[2];
  const float* W_out = (const float*)d_in[3];
  const float* b_out = (const float*)d_in[4];
  const float* rw    = (const float*)d_in[5];
  const float* rb    = (const float*)d_in[6];
  float* out = (float*)d_out;

  init_kernel<<<(out_size + 255) / 256, 256>>>(out, out_size);
  router_kernel<<<S_TOK, 256>>>(x, rw, rb);
  build_lists_kernel<<<1, 512>>>();
  aux_kernel<<<1, 32>>>(out, out_size);
  // GEMM1: grid x = FF/64 tiles, y = worst-case row tiles (2048/128), z = experts
  gemm1_kernel<<<dim3(FF / 64, S_TOK / 128, N_EXP), 256>>>(x, W_in, b_in);
  // GEMM2: grid x = H/128 tiles
  gemm2_kernel<<<dim3(H_DIM / 128, S_TOK / 128, N_EXP), 256>>>(W_out, b_out, out);
}